// round 14
// baseline (speedup 1.0000x reference)
#include <cuda_runtime.h>
#include <cstdint>

// CostVolume via single tf32 GEMM (mma.sync.m16n8k8.tf32; tcgen05 unavailable
// under virtual arch compute_103).
//
// out[b,h,j,i] = (1/128) * sum_c L[b,h,j,c]*R[b,h,j-i,c], j>=i else 0.
// Per CTA (bh, kt): D[m<128][n<64] = sum_c L[kt*64+m][c]*R[kt*64+n][c];
// out(j=kt*64+m, i=m-n) valid iff 0<=i<64; covered exactly once.
//
// B (R tile, 64 rows) is RESIDENT for all of K: loaded once in phase 0 via
// LDG+cvt.rna+STS.128. A (L tile, 128 rows) is processed in 2 half-K phases
// via cp.async (raw f32 bits; tf32 HMMA truncates internally; truncation
// noise cancels over K -> rel_err ~4.6e-4). Phase 1 waits ONLY on 8 A
// cp.asyncs (no B chain).
//
// Pair-packed conflict-free smem layout (saves padding vs stride-80):
// rows stored in pairs, odd row offset +64B (half a bank cycle):
//   A: rowbase(m) = (m>>1)*576 + (m&1)*320, row = 64 floats (256B)
//   B: rowbase(n) = (n>>1)*1088 + (n&1)*576, row = 128 floats (512B)
// Every 8-lane LDS.128 phase hits even-row bank group {0..12} and odd-row
// group {16..28} -> conflict-free. A 36864 + B 34816 = 71680B -> 3 CTAs/SM.
//
// Channel-permutation trick: K-sum invariant under channel permutations
// applied identically to A and B -> natural k-contiguous layout; LDS.128
// elements .x/.y feed k-step 2t (cols c/c+4), .z/.w feed 2t+1.
// Dead-warp skip: wid 3,4 have no valid outputs -> skip mainloop, write the
// kt==0 j<i zeros. lds128 volatile+memory-clobber (A addresses repeat
// across halves; CSE across barriers otherwise).

#define WW 320
#define CC 128
#define DD 64
#define PAIR_A 576
#define PAIR_B 1088
#define OFF_B  (64 * PAIR_A)                // 36864
#define SMEM_TOTAL (OFF_B + 32 * PAIR_B)    // 71680

__device__ __forceinline__ uint32_t smem_u32(const void* p) {
    uint32_t a;
    asm("{ .reg .u64 t; cvta.to.shared.u64 t, %1; cvt.u32.u64 %0, t; }" : "=r"(a) : "l"(p));
    return a;
}
__device__ __forceinline__ uint32_t f2tf32(float x) {
    uint32_t r;
    asm("cvt.rna.tf32.f32 %0, %1;" : "=r"(r) : "f"(x));
    return r;
}
__device__ __forceinline__ void cpasync16(uint32_t dst, const void* src) {
    asm volatile("cp.async.ca.shared.global [%0], [%1], 16;"
                 :: "r"(dst), "l"(src) : "memory");
}
__device__ __forceinline__ void sts128(uint32_t addr, uint32_t x, uint32_t y,
                                       uint32_t z, uint32_t w) {
    asm volatile("st.shared.v4.b32 [%0], {%1,%2,%3,%4};"
                 :: "r"(addr), "r"(x), "r"(y), "r"(z), "r"(w) : "memory");
}
__device__ __forceinline__ uint4 lds128(uint32_t addr) {
    uint4 v;
    asm volatile("ld.shared.v4.b32 {%0,%1,%2,%3}, [%4];"
                 : "=r"(v.x), "=r"(v.y), "=r"(v.z), "=r"(v.w)
                 : "r"(addr) : "memory");
    return v;
}
__device__ __forceinline__ void mma_tf32(float* d, uint32_t a0, uint32_t a1,
                                         uint32_t a2, uint32_t a3,
                                         uint32_t b0, uint32_t b1) {
    asm volatile(
        "mma.sync.aligned.m16n8k8.row.col.f32.tf32.tf32.f32 "
        "{%0,%1,%2,%3}, {%4,%5,%6,%7}, {%8,%9}, {%0,%1,%2,%3};"
        : "+f"(d[0]), "+f"(d[1]), "+f"(d[2]), "+f"(d[3])
        : "r"(a0), "r"(a1), "r"(a2), "r"(a3), "r"(b0), "r"(b1));
}

__global__ __launch_bounds__(256, 3)
void cv_tf32_kernel(const float* __restrict__ L, const float* __restrict__ R,
                    float* __restrict__ out) {
    extern __shared__ char smem[];
    const uint32_t sb = smem_u32(smem);
    const int tid = threadIdx.x;
    const int wid = tid >> 5;
    const int lid = tid & 31;
    const int kt = blockIdx.x;      // 0..4
    const int bh = blockIdx.y;      // 0..1279

    const float* Lg = L + (size_t)bh * WW * CC;
    const float* Rg = R + (size_t)bh * WW * CC;
    float* og = out + (size_t)bh * WW * DD;

    const int wm = wid & 3;
    const int wn = wid >> 2;
    const bool work = (wid != 3) && (wid != 4);   // band-dead warps
    const int lr = lid >> 2;
    const int lc = lid & 3;
    // pair-packed lane bases (parity = lr&1; 8-row step = 4 pairs)
    const uint32_t aBase = sb + (uint32_t)(((wm * 32 + lr) >> 1) * PAIR_A
                                           + (lr & 1) * 320 + lc * 16);
    const uint32_t bBase = sb + OFF_B + (uint32_t)(((wn * 32 + lr) >> 1) * PAIR_B
                                                   + (lr & 1) * 576 + lc * 16);
    const uint32_t A8 = 4 * PAIR_A;   // 2304
    const uint32_t B8 = 4 * PAIR_B;   // 4352

    const int g  = tid & 15;          // A: 16B chunk (channels 4g..4g+3 of half)
    const int m0 = tid >> 4;          // A: row 0..15, stride 16
    const int g2 = tid & 31;          // B: 16B chunk of full-K row
    const int n0 = tid >> 5;          // B: row 0..7, stride 8

    float acc[2][4][4];
    #pragma unroll
    for (int mf = 0; mf < 2; mf++)
        #pragma unroll
        for (int nf = 0; nf < 4; nf++)
            #pragma unroll
            for (int c = 0; c < 4; c++) acc[mf][nf][c] = 0.f;

    #pragma unroll
    for (int kh = 0; kh < 2; kh++) {
        if (kh) __syncthreads();      // drain A readers before overwriting

        // ---- A half-K via cp.async (raw f32) ----
        {
            const int csrc = kh * 64 + g * 4;
            uint32_t dstA = sb + (uint32_t)((m0 >> 1) * PAIR_A + (m0 & 1) * 320 + g * 16);
            #pragma unroll
            for (int it = 0; it < 8; it++) {
                int j = kt * 64 + m0 + it * 16;
                if (j > WW - 1) j = WW - 1;   // overrun rows pruned at store
                cpasync16(dstA, Lg + (size_t)j * CC + csrc);
                dstA += 8 * PAIR_A;           // 16 rows = 8 pairs
            }
            asm volatile("cp.async.commit_group;" ::: "memory");
        }
        // ---- B full-K once (phase 0): LDG.128 -> cvt.rna -> STS.128 ----
        if (kh == 0) {
            uint32_t dstB = sb + OFF_B + (uint32_t)((n0 >> 1) * PAIR_B + (n0 & 1) * 576 + g2 * 16);
            const float4* srcB = (const float4*)(Rg + (size_t)(kt * 64 + n0) * CC) + g2;
            #pragma unroll
            for (int it = 0; it < 8; it++) {
                float4 v = __ldg(srcB);
                sts128(dstB, f2tf32(v.x), f2tf32(v.y), f2tf32(v.z), f2tf32(v.w));
                srcB += 8 * (CC / 4);
                dstB += 4 * PAIR_B;           // 8 rows = 4 pairs
            }
        }
        asm volatile("cp.async.wait_group 0;" ::: "memory");
        __syncthreads();

        if (work) {
            // ---- Mainloop: warp tile 32x32, 4 t-iters per half ----
            // LDS.128 elements: .x/.y -> k-step 2t (cols c/c+4), .z/.w -> 2t+1.
            const uint32_t bk = bBase + kh * 256;   // half-K offset within B row
            #pragma unroll
            for (int t = 0; t < 4; t++) {
                const uint32_t ko = t * 64;
                uint4 a0 = lds128(aBase + ko);
                uint4 a1 = lds128(aBase + A8 + ko);
                uint4 a2 = lds128(aBase + 2 * A8 + ko);
                uint4 a3 = lds128(aBase + 3 * A8 + ko);
                uint4 b0 = lds128(bk + ko);
                uint4 b1 = lds128(bk + B8 + ko);
                uint4 b2 = lds128(bk + 2 * B8 + ko);
                uint4 b3 = lds128(bk + 3 * B8 + ko);
                mma_tf32(acc[0][0], a0.x, a1.x, a0.y, a1.y, b0.x, b0.y);
                mma_tf32(acc[0][1], a0.x, a1.x, a0.y, a1.y, b1.x, b1.y);
                mma_tf32(acc[0][2], a0.x, a1.x, a0.y, a1.y, b2.x, b2.y);
                mma_tf32(acc[0][3], a0.x, a1.x, a0.y, a1.y, b3.x, b3.y);
                mma_tf32(acc[1][0], a2.x, a3.x, a2.y, a3.y, b0.x, b0.y);
                mma_tf32(acc[1][1], a2.x, a3.x, a2.y, a3.y, b1.x, b1.y);
                mma_tf32(acc[1][2], a2.x, a3.x, a2.y, a3.y, b2.x, b2.y);
                mma_tf32(acc[1][3], a2.x, a3.x, a2.y, a3.y, b3.x, b3.y);
                mma_tf32(acc[0][0], a0.z, a1.z, a0.w, a1.w, b0.z, b0.w);
                mma_tf32(acc[0][1], a0.z, a1.z, a0.w, a1.w, b1.z, b1.w);
                mma_tf32(acc[0][2], a0.z, a1.z, a0.w, a1.w, b2.z, b2.w);
                mma_tf32(acc[0][3], a0.z, a1.z, a0.w, a1.w, b3.z, b3.w);
                mma_tf32(acc[1][0], a2.z, a3.z, a2.w, a3.w, b0.z, b0.w);
                mma_tf32(acc[1][1], a2.z, a3.z, a2.w, a3.w, b1.z, b1.w);
                mma_tf32(acc[1][2], a2.z, a3.z, a2.w, a3.w, b2.z, b2.w);
                mma_tf32(acc[1][3], a2.z, a3.z, a2.w, a3.w, b3.z, b3.w);
            }
        } else if (kh == 0 && kt == 0) {
            // idle warps write the j<i zeros concurrently (disjoint addresses)
            int j = tid - 96;       // tid in [96,160) -> j 0..63
            for (int i = j + 1; i < 64; i++)
                og[(size_t)j * DD + i] = 0.f;
        }
    }

    // ---- Epilogue: direct predicated stores (L2 merges spans) ----
    if (work) {
        const float inv = 1.0f / 128.0f;
        const int mrow = wm * 32 + lr;
        const int ncol = wn * 32 + lc * 2;
        const int jrow = kt * 64 + mrow;
        #pragma unroll
        for (int mf = 0; mf < 2; mf++) {
            #pragma unroll
            for (int c2 = 0; c2 < 2; c2++) {
                int j = jrow + mf * 16 + c2 * 8;
                if (j >= WW) continue;
                int m = j - kt * 64;
                float* orow = og + (size_t)j * DD;
                #pragma unroll
                for (int nf = 0; nf < 4; nf++) {
                    #pragma unroll
                    for (int c1 = 0; c1 < 2; c1++) {
                        int n = ncol + nf * 8 + c1;
                        int i = m - n;
                        if (i >= 0 && i < 64)
                            orow[i] = acc[mf][nf][c2 * 2 + c1] * inv;
                    }
                }
            }
        }
    }
}

extern "C" void kernel_launch(void* const* d_in, const int* in_sizes, int n_in,
                              void* d_out, int out_size) {
    const float* left  = (const float*)d_in[0];
    const float* right = (const float*)d_in[1];
    float* out = (float*)d_out;

    cudaFuncSetAttribute(cv_tf32_kernel,
                         cudaFuncAttributeMaxDynamicSharedMemorySize, SMEM_TOTAL);
    dim3 grid(5, 8 * 160);   // (kt, bh)
    cv_tf32_kernel<<<grid, 256, SMEM_TOTAL>>>(left, right, out);
}

// round 15
// speedup vs baseline: 1.2695x; 1.2695x over previous
#include <cuda_runtime.h>
#include <cstdint>

// CostVolume via single tf32 GEMM (mma.sync.m16n8k8.tf32; tcgen05 unavailable
// under virtual arch compute_103).
//
// out[b,h,j,i] = (1/128) * sum_c L[b,h,j,c]*R[b,h,j-i,c], j>=i else 0.
// Per CTA (bh, kt): D[m<128][n<64] = sum_c L[kt*64+m][c]*R[kt*64+n][c];
// out(j=kt*64+m, i=m-n) valid iff 0<=i<64; covered exactly once.
//
// Structure = round-11 optimum (measured 120.4us; rounds 12/13/14 structural
// variants all regressed): 2 sequential half-K phases reusing one 60KB smem
// buffer -> 3 CTAs/SM. A via cp.async (raw f32 bits; tf32 HMMA truncates,
// noise cancels over K), B via LDG+cvt.rna+STS.128 overlapping the A copies.
// Micro-trim this round: A-prologue row clamp hoisted out of the loop
// (only kt==4 needs it) -> pure pointer-march for 4/5 of CTAs.
//
// Channel-permutation trick: K-sum invariant under channel permutations
// applied identically to A and B -> natural k-contiguous smem layout;
// LDS.128 elements .x/.y feed k-step 2t (cols c/c+4), .z/.w feed 2t+1.
// Row stride 80 floats: conflict-free LDS.128 phases. Dead-warp skip:
// wid 3,4 have no valid outputs -> skip mainloop, write kt==0 j<i zeros.
// lds128 volatile+memory-clobber (addresses repeat across halves).

#define WW 320
#define CC 128
#define DD 64
#define RSF 80
#define OFF_A 0
#define OFF_B (128 * RSF * 4)               // 40960
#define SMEM_TOTAL (OFF_B + 64 * RSF * 4)   // 61440
#define ROWB (RSF * 4)                      // 320 bytes per row

__device__ __forceinline__ uint32_t smem_u32(const void* p) {
    uint32_t a;
    asm("{ .reg .u64 t; cvta.to.shared.u64 t, %1; cvt.u32.u64 %0, t; }" : "=r"(a) : "l"(p));
    return a;
}
__device__ __forceinline__ uint32_t f2tf32(float x) {
    uint32_t r;
    asm("cvt.rna.tf32.f32 %0, %1;" : "=r"(r) : "f"(x));
    return r;
}
__device__ __forceinline__ void cpasync16(uint32_t dst, const void* src) {
    asm volatile("cp.async.ca.shared.global [%0], [%1], 16;"
                 :: "r"(dst), "l"(src) : "memory");
}
__device__ __forceinline__ void sts128(uint32_t addr, uint32_t x, uint32_t y,
                                       uint32_t z, uint32_t w) {
    asm volatile("st.shared.v4.b32 [%0], {%1,%2,%3,%4};"
                 :: "r"(addr), "r"(x), "r"(y), "r"(z), "r"(w) : "memory");
}
__device__ __forceinline__ uint4 lds128(uint32_t addr) {
    uint4 v;
    asm volatile("ld.shared.v4.b32 {%0,%1,%2,%3}, [%4];"
                 : "=r"(v.x), "=r"(v.y), "=r"(v.z), "=r"(v.w)
                 : "r"(addr) : "memory");
    return v;
}
__device__ __forceinline__ void mma_tf32(float* d, uint32_t a0, uint32_t a1,
                                         uint32_t a2, uint32_t a3,
                                         uint32_t b0, uint32_t b1) {
    asm volatile(
        "mma.sync.aligned.m16n8k8.row.col.f32.tf32.tf32.f32 "
        "{%0,%1,%2,%3}, {%4,%5,%6,%7}, {%8,%9}, {%0,%1,%2,%3};"
        : "+f"(d[0]), "+f"(d[1]), "+f"(d[2]), "+f"(d[3])
        : "r"(a0), "r"(a1), "r"(a2), "r"(a3), "r"(b0), "r"(b1));
}

__global__ __launch_bounds__(256, 3)
void cv_tf32_kernel(const float* __restrict__ L, const float* __restrict__ R,
                    float* __restrict__ out) {
    extern __shared__ char smem[];
    const uint32_t sb = smem_u32(smem);
    const int tid = threadIdx.x;
    const int wid = tid >> 5;
    const int lid = tid & 31;
    const int kt = blockIdx.x;      // 0..4
    const int bh = blockIdx.y;      // 0..1279

    const float* Lg = L + (size_t)bh * WW * CC;
    const float* Rg = R + (size_t)bh * WW * CC;
    float* og = out + (size_t)bh * WW * DD;

    const int wm = wid & 3;
    const int wn = wid >> 2;
    const bool work = (wid != 3) && (wid != 4);   // band-dead warps
    const int lr = lid >> 2;
    const int lc = lid & 3;
    const uint32_t aBase = sb + OFF_A + (uint32_t)((wm * 32 + lr) * ROWB + lc * 16);
    const uint32_t bBase = sb + OFF_B + (uint32_t)((wn * 32 + lr) * ROWB + lc * 16);
    const uint32_t R8 = 8 * ROWB;   // 2560

    const int g  = tid & 15;        // 16B chunk: channels 4g..4g+3 of the half
    const int m0 = tid >> 4;        // starting row, stride 16

    float acc[2][4][4];
    #pragma unroll
    for (int mf = 0; mf < 2; mf++)
        #pragma unroll
        for (int nf = 0; nf < 4; nf++)
            #pragma unroll
            for (int c = 0; c < 4; c++) acc[mf][nf][c] = 0.f;

    #pragma unroll
    for (int kh = 0; kh < 2; kh++) {
        if (kh) __syncthreads();    // drain readers before overwriting smem

        // ---- Prologue: A via cp.async (raw f32), B via LDG+cvt.rna+STS.128 ----
        {
            const int csrc = kh * 64 + g * 4;
            uint32_t dstA = sb + OFF_A + (uint32_t)(m0 * ROWB + g * 16);
            if (kt < 4) {
                // no clamp needed: max row = 3*64 + 15 + 112 = 319
                const float* srcA = Lg + (size_t)(kt * 64 + m0) * CC + csrc;
                #pragma unroll
                for (int it = 0; it < 8; it++) {
                    cpasync16(dstA, srcA);
                    srcA += 16 * CC;
                    dstA += 16 * ROWB;
                }
            } else {
                #pragma unroll
                for (int it = 0; it < 8; it++) {
                    int j = 256 + m0 + it * 16;
                    if (j > WW - 1) j = WW - 1;   // overrun rows pruned at store
                    cpasync16(dstA, Lg + (size_t)j * CC + csrc);
                    dstA += 16 * ROWB;
                }
            }
            asm volatile("cp.async.commit_group;" ::: "memory");
            // B: LDG.128 -> cvt.rna x4 -> STS.128 (overlaps the async copies)
            uint32_t dstB = sb + OFF_B + (uint32_t)(m0 * ROWB + g * 16);
            const float4* srcB = (const float4*)(Rg + (size_t)(kt * 64 + m0) * CC + csrc);
            #pragma unroll
            for (int it = 0; it < 4; it++) {
                float4 v = __ldg(srcB);
                sts128(dstB, f2tf32(v.x), f2tf32(v.y), f2tf32(v.z), f2tf32(v.w));
                srcB += 16 * (CC / 4);
                dstB += 16 * ROWB;
            }
            asm volatile("cp.async.wait_group 0;" ::: "memory");
        }
        __syncthreads();

        if (work) {
            // ---- Mainloop: warp tile 32x32, 4 t-iters per half ----
            // LDS.128 elements: .x/.y -> k-step 2t (cols c/c+4), .z/.w -> 2t+1.
            #pragma unroll
            for (int t = 0; t < 4; t++) {
                const uint32_t ko = t * 64;
                uint4 a0 = lds128(aBase + ko);
                uint4 a1 = lds128(aBase + R8 + ko);
                uint4 a2 = lds128(aBase + 2 * R8 + ko);
                uint4 a3 = lds128(aBase + 3 * R8 + ko);
                uint4 b0 = lds128(bBase + ko);
                uint4 b1 = lds128(bBase + R8 + ko);
                uint4 b2 = lds128(bBase + 2 * R8 + ko);
                uint4 b3 = lds128(bBase + 3 * R8 + ko);
                mma_tf32(acc[0][0], a0.x, a1.x, a0.y, a1.y, b0.x, b0.y);
                mma_tf32(acc[0][1], a0.x, a1.x, a0.y, a1.y, b1.x, b1.y);
                mma_tf32(acc[0][2], a0.x, a1.x, a0.y, a1.y, b2.x, b2.y);
                mma_tf32(acc[0][3], a0.x, a1.x, a0.y, a1.y, b3.x, b3.y);
                mma_tf32(acc[1][0], a2.x, a3.x, a2.y, a3.y, b0.x, b0.y);
                mma_tf32(acc[1][1], a2.x, a3.x, a2.y, a3.y, b1.x, b1.y);
                mma_tf32(acc[1][2], a2.x, a3.x, a2.y, a3.y, b2.x, b2.y);
                mma_tf32(acc[1][3], a2.x, a3.x, a2.y, a3.y, b3.x, b3.y);
                mma_tf32(acc[0][0], a0.z, a1.z, a0.w, a1.w, b0.z, b0.w);
                mma_tf32(acc[0][1], a0.z, a1.z, a0.w, a1.w, b1.z, b1.w);
                mma_tf32(acc[0][2], a0.z, a1.z, a0.w, a1.w, b2.z, b2.w);
                mma_tf32(acc[0][3], a0.z, a1.z, a0.w, a1.w, b3.z, b3.w);
                mma_tf32(acc[1][0], a2.z, a3.z, a2.w, a3.w, b0.z, b0.w);
                mma_tf32(acc[1][1], a2.z, a3.z, a2.w, a3.w, b1.z, b1.w);
                mma_tf32(acc[1][2], a2.z, a3.z, a2.w, a3.w, b2.z, b2.w);
                mma_tf32(acc[1][3], a2.z, a3.z, a2.w, a3.w, b3.z, b3.w);
            }
        } else if (kh == 0 && kt == 0) {
            // idle warps write the j<i zeros concurrently (disjoint addresses)
            int j = tid - 96;       // tid in [96,160) -> j 0..63
            for (int i = j + 1; i < 64; i++)
                og[(size_t)j * DD + i] = 0.f;
        }
    }

    // ---- Epilogue: direct predicated stores (L2 merges spans) ----
    if (work) {
        const float inv = 1.0f / 128.0f;
        const int mrow = wm * 32 + lr;
        const int ncol = wn * 32 + lc * 2;
        const int jrow = kt * 64 + mrow;
        #pragma unroll
        for (int mf = 0; mf < 2; mf++) {
            #pragma unroll
            for (int c2 = 0; c2 < 2; c2++) {
                int j = jrow + mf * 16 + c2 * 8;
                if (j >= WW) continue;
                int m = j - kt * 64;
                float* orow = og + (size_t)j * DD;
                #pragma unroll
                for (int nf = 0; nf < 4; nf++) {
                    #pragma unroll
                    for (int c1 = 0; c1 < 2; c1++) {
                        int n = ncol + nf * 8 + c1;
                        int i = m - n;
                        if (i >= 0 && i < 64)
                            orow[i] = acc[mf][nf][c2 * 2 + c1] * inv;
                    }
                }
            }
        }
    }
}

extern "C" void kernel_launch(void* const* d_in, const int* in_sizes, int n_in,
                              void* d_out, int out_size) {
    const float* left  = (const float*)d_in[0];
    const float* right = (const float*)d_in[1];
    float* out = (float*)d_out;

    cudaFuncSetAttribute(cv_tf32_kernel,
                         cudaFuncAttributeMaxDynamicSharedMemorySize, SMEM_TOTAL);
    dim3 grid(5, 8 * 160);   // (kt, bh)
    cv_tf32_kernel<<<grid, 256, SMEM_TOTAL>>>(left, right, out);
}